// round 14
// baseline (speedup 1.0000x reference)
#include <cuda_runtime.h>
#include <cuda_fp16.h>
#include <cstdint>

// ---------------- problem constants ----------------
#define KH_ 9
#define KW_ 9
#define IC_ 25
#define OC_ 100
#define H_  256
#define W_  256
#define OH_ 248
#define OW_ 248
#define B_  8

// ---------------- GEMM config ----------------
#define KWP 10            // kw padded 9 -> 10
#define NOC 104           // oc padded 100 -> 104 (13 n8 chunks: 7 + 6 per warp col)
#define NTHR 512          // 16 warps; M = 256 px (2 output rows x 128)
#define NAROWS 26         // 25 ic + zero row for k-pad

// B full-K tiles: 256 k-elems (250 real + pad), pitch 264 = 528 B (4-bank stride)
#define BPITCH 264
#define BROWB  528
#define BTILE  (NOC*BROWB)       // 54912 B
#define NSEG   9                 // one segment per kh (full K)

// A: per input row, even + odd-shift parity copies; 4-slot ring keyed by row&3
#define APITCH 144
#define AROWB (APITCH*2)         // 288 B
#define ACOPY (NAROWS*AROWB)     // 7488
#define ASLOT (2*ACOPY)          // 14976
#define GA_P  264                // padded row length of pre-converted A

// smem layout (bytes)
#define SM_BIAS 0                            // 104 * 4 = 416 B
#define SM_LUT  448                          // 4 c4-variants * 16 kc * 8 B = 512 B
#define SM_A    1024                         // 4 A slots
#define SM_B    (SM_A + 4*ASLOT)             // 1024 + 59904 = 60928
#define SMEM_TOTAL (SM_B + 3*BTILE)          // 60928 + 164736 = 225664

// fp16 weights: [kh][oc][k(264)]
__device__ __align__(16) __half g_w[KH_][NOC][BPITCH];
// pre-converted fp16 input, even + odd-shift parity copies
__device__ __align__(16) __half g_ae[B_][IC_][H_][GA_P];
__device__ __align__(16) __half g_ao[B_][IC_][H_][GA_P];

// ---------------- helpers ----------------
__device__ __forceinline__ uint32_t smem_u32(const void* p) {
    uint32_t a;
    asm("{ .reg .u64 t; cvta.to.shared.u64 t, %1; cvt.u32.u64 %0, t; }" : "=r"(a) : "l"(p));
    return a;
}

__device__ __forceinline__ uint32_t lds32(uint32_t a) {
    uint32_t v;
    asm volatile("ld.shared.b32 %0, [%1];" : "=r"(v) : "r"(a));
    return v;
}

__device__ __forceinline__ void lds64v(uint32_t& v0, uint32_t& v1, uint32_t a) {
    asm volatile("ld.shared.v2.u32 {%0,%1}, [%2];" : "=r"(v0), "=r"(v1) : "r"(a));
}

__device__ __forceinline__ void ldmx4(uint32_t& r0, uint32_t& r1, uint32_t& r2,
                                      uint32_t& r3, uint32_t addr) {
    asm volatile("ldmatrix.sync.aligned.m8n8.x4.shared.b16 {%0,%1,%2,%3}, [%4];"
                 : "=r"(r0), "=r"(r1), "=r"(r2), "=r"(r3) : "r"(addr));
}

__device__ __forceinline__ void ldmx2(uint32_t& r0, uint32_t& r1, uint32_t addr) {
    asm volatile("ldmatrix.sync.aligned.m8n8.x2.shared.b16 {%0,%1}, [%2];"
                 : "=r"(r0), "=r"(r1) : "r"(addr));
}

__device__ __forceinline__ void mma16816(float* d, const uint32_t* a,
                                         uint32_t b0, uint32_t b1) {
    asm volatile(
        "mma.sync.aligned.m16n8k16.row.col.f32.f16.f16.f32 "
        "{%0,%1,%2,%3}, {%4,%5,%6,%7}, {%8,%9}, {%0,%1,%2,%3};"
        : "+f"(d[0]), "+f"(d[1]), "+f"(d[2]), "+f"(d[3])
        : "r"(a[0]), "r"(a[1]), "r"(a[2]), "r"(a[3]), "r"(b0), "r"(b1));
}

__device__ __forceinline__ void cpasync16(uint32_t dst, const void* src) {
    asm volatile("cp.async.cg.shared.global [%0], [%1], 16;"
                 :: "r"(dst), "l"(src));
}

// ---------------- merged prep: weights + input fp16 parity copies ----------------
__global__ void prep_all(const float* __restrict__ wt,
                         const float* __restrict__ pic) {
    const long long idx = (long long)blockIdx.x * blockDim.x + threadIdx.x;

    // weights part
    const int NW = KH_ * NOC * BPITCH;
    if (idx < NW) {
        int i  = (int)idx;
        int kh = i / (NOC * BPITCH);
        int rem = i % (NOC * BPITCH);
        int oc = rem / BPITCH;
        int k  = rem % BPITCH;
        float w = 0.f;
        if (oc < OC_ && k < IC_ * KWP) {
            int ic = k / KWP, kw = k % KWP;
            if (kw < KW_)
                w = wt[(((size_t)oc * IC_ + ic) * KH_ + kh) * KW_ + kw];
        }
        g_w[kh][oc][k] = __float2half_rn(w);
    }

    // input part
    const long long total = (long long)B_ * IC_ * H_ * GA_P;
    if (idx < total) {
        int c = (int)(idx % GA_P);
        long long r = idx / GA_P;        // (b*IC + ic)*H + row
        const float* prow = pic + r * W_;
        __half ve = __float2half_rn(c < W_ ? prow[c] : 0.f);
        __half vo = __float2half_rn(c + 1 < W_ ? prow[c + 1] : 0.f);
        ((__half*)g_ae)[idx] = ve;
        ((__half*)g_ao)[idx] = vo;
    }
}

// ---------------- main kernel ----------------
// block = 256 px (2 output rows x 128) x 104 oc.
// 16 warps: wm = wid&7 (rowi = wm>>2, wmr = wm&3 -> 2 m16-frags),
//           wn = wid>>3 (7 or 6 n8-chunks).
// 9 segments (one per kh, full K=256). B ring-3, A 4-slot ring (row&3),
// one new A input-row set staged per kh. cp.async prefetch distance 2.
// Per-kc A k-offsets come from a 512B smem LUT (segment-invariant).
__global__ __launch_bounds__(NTHR, 1)
void conv_hmma(const float* __restrict__ bias,
               float* __restrict__ out) {
    extern __shared__ char smem[];
    const uint32_t sb = smem_u32(smem);
    const int tid = threadIdx.x;
    const int lid = tid & 31;
    const int wid = tid >> 5;
    const int wm  = wid & 7;
    const int wn  = wid >> 3;
    const int rowi = wm >> 2;         // 0: output row y0, 1: output row y0+1
    const int wmr  = wm & 3;
    const int g  = lid >> 2;          // 0..7
    const int c4 = (lid & 3) << 1;    // 0,2,4,6
    const int x0 = blockIdx.x ? (OW_ - 128) : 0;
    const int y0 = blockIdx.y * 2;
    const int b  = blockIdx.z;

    // ---- init: zero A slots (pads + zero row persist), bias, koff LUT ----
#pragma unroll 1
    for (int i = tid; i < (4 * ASLOT) / 16; i += NTHR)
        *(uint4*)(smem + SM_A + i * 16) = make_uint4(0, 0, 0, 0);
    if (tid < NOC)
        *(float*)(smem + SM_BIAS + tid * 4) = (tid < OC_) ? bias[tid] : 0.f;
    if (tid < 64) {
        int kc  = tid >> 2;
        int cv  = (tid & 3) << 1;
        int k0  = kc * 16 + cv;
        int k1  = k0 + 8;
        int ic0 = k0 / KWP, ic1 = k1 / KWP;
        uint32_t koff0 = (uint32_t)(ic0 * AROWB + (k0 - ic0 * KWP) * 2);
        uint32_t koff1 = (uint32_t)(ic1 * AROWB + (k1 - ic1 * KWP) * 2);
        *(uint2*)(smem + SM_LUT + (tid & 3) * 128 + kc * 8) = make_uint2(koff0, koff1);
    }
    __syncthreads();   // zeroing + LUT visible before cp.async / compute

    // stage input row r into slot (r&3): 2 parities * 25 ic * 17 x 16B
#define STAGE_A_ROW(r)                                                          \
    {                                                                           \
        const uint32_t adst = sb + SM_A + (uint32_t)(((r) & 3) * ASLOT);        \
        _Pragma("unroll 1")                                                     \
        for (int i = tid; i < 2 * IC_ * 17; i += NTHR) {                        \
            int p  = i / (IC_ * 17);                                            \
            int rr = i % (IC_ * 17);                                            \
            int ic = rr / 17;                                                   \
            int ch = rr % 17;                                                   \
            const __half* src = (p ? &g_ao[0][0][0][0] : &g_ae[0][0][0][0])     \
                + ((((size_t)b * IC_ + ic) * H_) + (r)) * GA_P + x0 + ch * 8;   \
            cpasync16(adst + (uint32_t)(p * ACOPY + ic * AROWB + ch * 16), src);\
        }                                                                       \
    }

#define STAGE_B(kh, slot)                                                       \
    {                                                                           \
        const char* bsrc = (const char*)(&g_w[(kh)][0][0]);                     \
        const uint32_t bdst = sb + SM_B + (uint32_t)((slot) * BTILE);           \
        _Pragma("unroll 1")                                                     \
        for (int i = tid; i < BTILE / 16; i += NTHR)                            \
            cpasync16(bdst + (uint32_t)(i * 16), bsrc + i * 16);                \
    }

    // ---- prologue ----
    STAGE_A_ROW(y0);
    STAGE_A_ROW(y0 + 1);
    STAGE_B(0, 0);
    asm volatile("cp.async.commit_group;" ::: "memory");
    STAGE_A_ROW(y0 + 2);
    STAGE_B(1, 1);
    asm volatile("cp.async.commit_group;" ::: "memory");

    // ldmatrix per-thread addresses (within a B tile)
    const int cb0 = wn * 7;        // base n8 chunk: 0 (7 chunks) or 7 (6 chunks)
    const int grp = lid >> 3;      // 0..3
    const int tr  = lid & 7;
    uint32_t bro[3];
#pragma unroll
    for (int j = 0; j < 3; ++j)
        bro[j] = (uint32_t)(((cb0 + 2 * j + (grp >> 1)) * 8 + tr) * BROWB
                            + (grp & 1) * 16);
    const uint32_t brx = (uint32_t)((6 * 8 + (lid & 7)) * BROWB
                                    + ((lid >> 3) & 1) * 16);   // chunk 6 (wn0 only)

    const uint32_t lutb = sb + SM_LUT + (uint32_t)((lid & 3) * 128);

    float acc[2][7][4];
#pragma unroll
    for (int m = 0; m < 2; ++m)
#pragma unroll
        for (int n = 0; n < 7; ++n)
#pragma unroll
            for (int q = 0; q < 4; ++q)
                acc[m][n][q] = 0.f;

    // ---- pipelined main loop: one segment per kh ----
#pragma unroll 1
    for (int s = 0; s < NSEG; ++s) {
        if (s < NSEG - 2) {
            asm volatile("cp.async.wait_group 1;" ::: "memory");
        } else {
            asm volatile("cp.async.wait_group 0;" ::: "memory");
        }
        __syncthreads();

        // prefetch segment s+2: B(kh=s+2) + new A input row y0+s+3
        if (s + 2 < NSEG) {
            STAGE_B(s + 2, (s + 2) % 3);
            STAGE_A_ROW(y0 + s + 3);
            asm volatile("cp.async.commit_group;" ::: "memory");
        }

        // ---- compute: 16 kc chunks, full K ----
        const int arow = y0 + s + rowi;                 // this warp's input row
        const uint32_t abase = sb + SM_A + (uint32_t)((arow & 3) * ASLOT)
                             + ((g & 1) ? (uint32_t)(ACOPY - 2) : 0u);
        uint32_t apx[2][2];
#pragma unroll
        for (int m = 0; m < 2; ++m)
#pragma unroll
            for (int h = 0; h < 2; ++h)
                apx[m][h] = abase + (uint32_t)(((wmr * 2 + m) * 16 + g + h * 8) * 2);

        const uint32_t qb = sb + SM_B + (uint32_t)((s % 3) * BTILE);

#pragma unroll
        for (int kc = 0; kc < 16; ++kc) {
            uint32_t koff0, koff1;
            lds64v(koff0, koff1, lutb + (uint32_t)(kc * 8));

            uint32_t a[2][4];
#pragma unroll
            for (int m = 0; m < 2; ++m) {
                a[m][0] = lds32(apx[m][0] + koff0);
                a[m][1] = lds32(apx[m][1] + koff0);
                a[m][2] = lds32(apx[m][0] + koff1);
                a[m][3] = lds32(apx[m][1] + koff1);
            }

            const uint32_t kb = (uint32_t)(kc * 32);
#pragma unroll
            for (int j = 0; j < 3; ++j) {
                uint32_t b0, b1, b2, b3;
                ldmx4(b0, b1, b2, b3, qb + bro[j] + kb);
                mma16816(acc[0][2 * j],     a[0], b0, b1);
                mma16816(acc[1][2 * j],     a[1], b0, b1);
                mma16816(acc[0][2 * j + 1], a[0], b2, b3);
                mma16816(acc[1][2 * j + 1], a[1], b2, b3);
            }
            if (wn == 0) {  // 7th chunk, first warp column only
                uint32_t e0, e1;
                ldmx2(e0, e1, qb + brx + kb);
                mma16816(acc[0][6], a[0], e0, e1);
                mma16816(acc[1][6], a[1], e0, e1);
            }
        }
    }

    // ---- epilogue: bias + stores ----
    const int nchunks = (wn == 0) ? 7 : 6;
    const int oy = y0 + rowi;
#pragma unroll
    for (int m = 0; m < 2; ++m) {
        const int px = (wmr * 2 + m) * 16 + g;
#pragma unroll
        for (int nc = 0; nc < 7; ++nc) {
            if (nc >= nchunks) break;
            const int oc = (cb0 + nc) * 8 + c4;
            if (oc < OC_) {
                float bz0 = *(float*)(smem + SM_BIAS + oc * 4);
                float bz1 = *(float*)(smem + SM_BIAS + (oc + 1) * 4);
                size_t base0 = (((size_t)(b * OC_ + oc)) * OH_ + oy) * OW_ + x0;
                size_t base1 = base0 + (size_t)OH_ * OW_;
                out[base0 + px]     = acc[m][nc][0] + bz0;
                out[base1 + px]     = acc[m][nc][1] + bz1;
                out[base0 + px + 8] = acc[m][nc][2] + bz0;
                out[base1 + px + 8] = acc[m][nc][3] + bz1;
            }
        }
    }
#undef STAGE_A_ROW
#undef STAGE_B
}

// ---------------- launch ----------------
extern "C" void kernel_launch(void* const* d_in, const int* in_sizes, int n_in,
                              void* d_out, int out_size) {
    const float* pic  = (const float*)d_in[0];   // [8,25,256,256]
    const float* wt   = (const float*)d_in[1];   // [100,25,9,9]
    const float* bias = (const float*)d_in[2];   // [100]
    float* out = (float*)d_out;                  // [8,100,248,248]

    long long n = (long long)B_ * IC_ * H_ * GA_P;   // covers weight part too
    prep_all<<<(int)((n + 255) / 256), 256>>>(wt, pic);

    cudaFuncSetAttribute(conv_hmma, cudaFuncAttributeMaxDynamicSharedMemorySize, SMEM_TOTAL);
    dim3 grid(2, OH_ / 2, B_);
    conv_hmma<<<grid, NTHR, SMEM_TOTAL>>>(bias, out);
}

// round 15
// speedup vs baseline: 1.0639x; 1.0639x over previous
#include <cuda_runtime.h>
#include <cuda_fp16.h>
#include <cstdint>

// ---------------- problem constants ----------------
#define KH_ 9
#define KW_ 9
#define IC_ 25
#define OC_ 100
#define H_  256
#define W_  256
#define OH_ 248
#define OW_ 248
#define B_  8

// ---------------- GEMM config ----------------
#define KWP 10            // kw padded 9 -> 10
#define NOC 104           // oc padded 100 -> 104 (13 n8 chunks: 6+6 +shared 13th)
#define NTHR 512          // 16 warps; M = 256 px (2 output rows x 128)
#define NAROWS 26         // 25 ic + zero row for k-pad

// B full-K tiles: 256 k-elems (250 real + pad), pitch 264 = 528 B (4-bank stride)
#define BPITCH 264
#define BROWB  528
#define BTILE  (NOC*BROWB)       // 54912 B
#define NSEG   9                 // one segment per kh (full K)

// A: per input row, even + odd-shift parity copies; 4-slot ring keyed by row&3
#define APITCH 144
#define AROWB (APITCH*2)         // 288 B
#define ACOPY (NAROWS*AROWB)     // 7488
#define ASLOT (2*ACOPY)          // 14976
#define GA_P  264                // padded row length of pre-converted A

// smem layout (bytes)
#define SM_BIAS 0                            // 104 * 4 = 416 B
#define SM_A    512                          // 4 A slots
#define SM_B    (SM_A + 4*ASLOT)             // 512 + 59904 = 60416
#define SMEM_TOTAL (SM_B + 3*BTILE)          // 60416 + 164736 = 225152

// fp16 weights: [kh][oc][k(264)]
__device__ __align__(16) __half g_w[KH_][NOC][BPITCH];
// pre-converted fp16 input, even + odd-shift parity copies
__device__ __align__(16) __half g_ae[B_][IC_][H_][GA_P];
__device__ __align__(16) __half g_ao[B_][IC_][H_][GA_P];

// ---------------- helpers ----------------
__device__ __forceinline__ uint32_t smem_u32(const void* p) {
    uint32_t a;
    asm("{ .reg .u64 t; cvta.to.shared.u64 t, %1; cvt.u32.u64 %0, t; }" : "=r"(a) : "l"(p));
    return a;
}

__device__ __forceinline__ uint32_t lds32(uint32_t a) {
    uint32_t v;
    asm volatile("ld.shared.b32 %0, [%1];" : "=r"(v) : "r"(a));
    return v;
}

__device__ __forceinline__ void ldmx4(uint32_t& r0, uint32_t& r1, uint32_t& r2,
                                      uint32_t& r3, uint32_t addr) {
    asm volatile("ldmatrix.sync.aligned.m8n8.x4.shared.b16 {%0,%1,%2,%3}, [%4];"
                 : "=r"(r0), "=r"(r1), "=r"(r2), "=r"(r3) : "r"(addr));
}

__device__ __forceinline__ void ldmx2(uint32_t& r0, uint32_t& r1, uint32_t addr) {
    asm volatile("ldmatrix.sync.aligned.m8n8.x2.shared.b16 {%0,%1}, [%2];"
                 : "=r"(r0), "=r"(r1) : "r"(addr));
}

__device__ __forceinline__ void mma16816(float* d, const uint32_t* a,
                                         uint32_t b0, uint32_t b1) {
    asm volatile(
        "mma.sync.aligned.m16n8k16.row.col.f32.f16.f16.f32 "
        "{%0,%1,%2,%3}, {%4,%5,%6,%7}, {%8,%9}, {%0,%1,%2,%3};"
        : "+f"(d[0]), "+f"(d[1]), "+f"(d[2]), "+f"(d[3])
        : "r"(a[0]), "r"(a[1]), "r"(a[2]), "r"(a[3]), "r"(b0), "r"(b1));
}

__device__ __forceinline__ void cpasync16(uint32_t dst, const void* src) {
    asm volatile("cp.async.cg.shared.global [%0], [%1], 16;"
                 :: "r"(dst), "l"(src));
}

// ---------------- merged prep: weights + vectorized input conversion ----------------
__global__ void prep_all(const float* __restrict__ wt,
                         const float* __restrict__ pic) {
    const int idx = blockIdx.x * blockDim.x + threadIdx.x;

    // weights part
    const int NW = KH_ * NOC * BPITCH;
    if (idx < NW) {
        int kh = idx / (NOC * BPITCH);
        int rem = idx % (NOC * BPITCH);
        int oc = rem / BPITCH;
        int k  = rem % BPITCH;
        float w = 0.f;
        if (oc < OC_ && k < IC_ * KWP) {
            int ic = k / KWP, kw = k % KWP;
            if (kw < KW_)
                w = wt[(((size_t)oc * IC_ + ic) * KH_ + kh) * KW_ + kw];
        }
        g_w[kh][oc][k] = __float2half_rn(w);
    }

    // input part: one thread converts 8 consecutive columns -> one uint4 per array
    const int total8 = B_ * IC_ * H_ * (GA_P / 8);   // 1,689,600
    if (idx < total8) {
        int chunk = idx % (GA_P / 8);
        int r     = idx / (GA_P / 8);       // (b*IC + ic)*H + row
        int c0    = chunk * 8;
        const float* prow = pic + (size_t)r * W_;
        ushort he[8], ho[8];
#pragma unroll
        for (int j = 0; j < 8; ++j) {
            int c = c0 + j;
            float ve = (c < W_) ? prow[c] : 0.f;
            float vo = (c + 1 < W_) ? prow[c + 1] : 0.f;
            he[j] = __half_as_ushort(__float2half_rn(ve));
            ho[j] = __half_as_ushort(__float2half_rn(vo));
        }
        size_t off = (size_t)r * GA_P + c0;
        *(uint4*)(((__half*)g_ae) + off) = *(uint4*)he;
        *(uint4*)(((__half*)g_ao) + off) = *(uint4*)ho;
    }
}

// ---------------- main kernel ----------------
// block = 256 px (2 output rows x 128) x 104 oc.
// 16 warps: wm = wid&7 (rowi = wm>>2, wmr = wm&3 -> 2 m16-frags),
//           wn = wid>>3. Each column owns 6 n8-chunks; the 13th (global
//           chunk 6) alternates by kc parity ((kc&1)==wn) and is reduced
//           across columns in the epilogue.
__global__ __launch_bounds__(NTHR, 1)
void conv_hmma(const float* __restrict__ bias,
               float* __restrict__ out) {
    extern __shared__ char smem[];
    const uint32_t sb = smem_u32(smem);
    const int tid = threadIdx.x;
    const int lid = tid & 31;
    const int wid = tid >> 5;
    const int wm  = wid & 7;
    const int wn  = wid >> 3;
    const int rowi = wm >> 2;         // 0: output row y0, 1: output row y0+1
    const int wmr  = wm & 3;
    const int g  = lid >> 2;          // 0..7
    const int c4 = (lid & 3) << 1;    // 0,2,4,6
    const int x0 = blockIdx.x ? (OW_ - 128) : 0;
    const int y0 = blockIdx.y * 2;
    const int b  = blockIdx.z;

    // ---- init: zero A slots (pads + zero row persist), stage bias ----
#pragma unroll 1
    for (int i = tid; i < (4 * ASLOT) / 16; i += NTHR)
        *(uint4*)(smem + SM_A + i * 16) = make_uint4(0, 0, 0, 0);
    if (tid < NOC)
        *(float*)(smem + SM_BIAS + tid * 4) = (tid < OC_) ? bias[tid] : 0.f;
    __syncthreads();   // zeroing visible before cp.async overwrites data region

    // stage input row r into slot (r&3): 2 parities * 25 ic * 17 x 16B
#define STAGE_A_ROW(r)                                                          \
    {                                                                           \
        const uint32_t adst = sb + SM_A + (uint32_t)(((r) & 3) * ASLOT);        \
        _Pragma("unroll 1")                                                     \
        for (int i = tid; i < 2 * IC_ * 17; i += NTHR) {                        \
            int p  = i / (IC_ * 17);                                            \
            int rr = i % (IC_ * 17);                                            \
            int ic = rr / 17;                                                   \
            int ch = rr % 17;                                                   \
            const __half* src = (p ? &g_ao[0][0][0][0] : &g_ae[0][0][0][0])     \
                + ((((size_t)b * IC_ + ic) * H_) + (r)) * GA_P + x0 + ch * 8;   \
            cpasync16(adst + (uint32_t)(p * ACOPY + ic * AROWB + ch * 16), src);\
        }                                                                       \
    }

#define STAGE_B(kh, slot)                                                       \
    {                                                                           \
        const char* bsrc = (const char*)(&g_w[(kh)][0][0]);                     \
        const uint32_t bdst = sb + SM_B + (uint32_t)((slot) * BTILE);           \
        _Pragma("unroll 1")                                                     \
        for (int i = tid; i < BTILE / 16; i += NTHR)                            \
            cpasync16(bdst + (uint32_t)(i * 16), bsrc + i * 16);                \
    }

    // ---- prologue ----
    STAGE_A_ROW(y0);
    STAGE_A_ROW(y0 + 1);
    STAGE_B(0, 0);
    asm volatile("cp.async.commit_group;" ::: "memory");
    STAGE_A_ROW(y0 + 2);
    STAGE_B(1, 1);
    asm volatile("cp.async.commit_group;" ::: "memory");

    // ldmatrix per-thread addresses (within a B tile)
    const int cb0 = wn * 7;        // chunks: wn0 -> 0..5 (+6 shared), wn1 -> 7..12 (+6 shared)
    const int grp = lid >> 3;      // 0..3
    const int tr  = lid & 7;
    uint32_t bro[3];
#pragma unroll
    for (int j = 0; j < 3; ++j)
        bro[j] = (uint32_t)(((cb0 + 2 * j + (grp >> 1)) * 8 + tr) * BROWB
                            + (grp & 1) * 16);
    const uint32_t brx = (uint32_t)((6 * 8 + (lid & 7)) * BROWB
                                    + ((lid >> 3) & 1) * 16);   // shared chunk 6

    float acc[2][7][4];
#pragma unroll
    for (int m = 0; m < 2; ++m)
#pragma unroll
        for (int n = 0; n < 7; ++n)
#pragma unroll
            for (int q = 0; q < 4; ++q)
                acc[m][n][q] = 0.f;

    // ---- pipelined main loop: one segment per kh ----
#pragma unroll 1
    for (int s = 0; s < NSEG; ++s) {
        if (s < NSEG - 2) {
            asm volatile("cp.async.wait_group 1;" ::: "memory");
        } else {
            asm volatile("cp.async.wait_group 0;" ::: "memory");
        }
        __syncthreads();

        // prefetch segment s+2: B(kh=s+2) + new A input row y0+s+3
        if (s + 2 < NSEG) {
            STAGE_B(s + 2, (s + 2) % 3);
            STAGE_A_ROW(y0 + s + 3);
            asm volatile("cp.async.commit_group;" ::: "memory");
        }

        // ---- compute: 16 kc chunks, full K ----
        const int arow = y0 + s + rowi;                 // this warp's input row
        const uint32_t abase = sb + SM_A + (uint32_t)((arow & 3) * ASLOT)
                             + ((g & 1) ? (uint32_t)(ACOPY - 2) : 0u);
        uint32_t apx[2][2];
#pragma unroll
        for (int m = 0; m < 2; ++m)
#pragma unroll
            for (int h = 0; h < 2; ++h)
                apx[m][h] = abase + (uint32_t)(((wmr * 2 + m) * 16 + g + h * 8) * 2);

        const uint32_t qb = sb + SM_B + (uint32_t)((s % 3) * BTILE);

#pragma unroll
        for (int kc = 0; kc < 16; ++kc) {
            const int k0 = kc * 16 + c4;
            const int k1 = k0 + 8;
            const int ic0 = (k0 * 6554) >> 16;   // /10
            const int ic1 = (k1 * 6554) >> 16;
            const uint32_t koff0 = (uint32_t)(ic0 * AROWB + (k0 - ic0 * KWP) * 2);
            const uint32_t koff1 = (uint32_t)(ic1 * AROWB + (k1 - ic1 * KWP) * 2);

            uint32_t a[2][4];
#pragma unroll
            for (int m = 0; m < 2; ++m) {
                a[m][0] = lds32(apx[m][0] + koff0);
                a[m][1] = lds32(apx[m][1] + koff0);
                a[m][2] = lds32(apx[m][0] + koff1);
                a[m][3] = lds32(apx[m][1] + koff1);
            }

            const uint32_t kb = (uint32_t)(kc * 32);
#pragma unroll
            for (int j = 0; j < 3; ++j) {
                uint32_t b0, b1, b2, b3;
                ldmx4(b0, b1, b2, b3, qb + bro[j] + kb);
                mma16816(acc[0][2 * j],     a[0], b0, b1);
                mma16816(acc[1][2 * j],     a[1], b0, b1);
                mma16816(acc[0][2 * j + 1], a[0], b2, b3);
                mma16816(acc[1][2 * j + 1], a[1], b2, b3);
            }
            if ((kc & 1) == wn) {   // shared chunk 6, alternating by kc parity
                uint32_t e0, e1;
                ldmx2(e0, e1, qb + brx + kb);
                mma16816(acc[0][6], a[0], e0, e1);
                mma16816(acc[1][6], a[1], e0, e1);
            }
        }
    }

    // ---- cross-column reduction for shared chunk 6 ----
    __syncthreads();   // all compute done; B slots reusable
    float* red = (float*)(smem + SM_B);
    if (wn == 1) {
#pragma unroll
        for (int m = 0; m < 2; ++m)
#pragma unroll
            for (int q = 0; q < 4; ++q)
                red[((wm * 2 + m) * 32 + lid) * 4 + q] = acc[m][6][q];
    }
    __syncthreads();
    if (wn == 0) {
#pragma unroll
        for (int m = 0; m < 2; ++m)
#pragma unroll
            for (int q = 0; q < 4; ++q)
                acc[m][6][q] += red[((wm * 2 + m) * 32 + lid) * 4 + q];
    }

    // ---- epilogue: bias + stores ----
    const int nchunks = (wn == 0) ? 7 : 6;
    const int oy = y0 + rowi;
#pragma unroll
    for (int m = 0; m < 2; ++m) {
        const int px = (wmr * 2 + m) * 16 + g;
#pragma unroll
        for (int nc = 0; nc < 7; ++nc) {
            if (nc >= nchunks) break;
            const int oc = (cb0 + nc) * 8 + c4;
            if (oc < OC_) {
                float bz0 = *(float*)(smem + SM_BIAS + oc * 4);
                float bz1 = *(float*)(smem + SM_BIAS + (oc + 1) * 4);
                size_t base0 = (((size_t)(b * OC_ + oc)) * OH_ + oy) * OW_ + x0;
                size_t base1 = base0 + (size_t)OH_ * OW_;
                out[base0 + px]     = acc[m][nc][0] + bz0;
                out[base1 + px]     = acc[m][nc][1] + bz1;
                out[base0 + px + 8] = acc[m][nc][2] + bz0;
                out[base1 + px + 8] = acc[m][nc][3] + bz1;
            }
        }
    }
#undef STAGE_A_ROW
#undef STAGE_B
}

// ---------------- launch ----------------
extern "C" void kernel_launch(void* const* d_in, const int* in_sizes, int n_in,
                              void* d_out, int out_size) {
    const float* pic  = (const float*)d_in[0];   // [8,25,256,256]
    const float* wt   = (const float*)d_in[1];   // [100,25,9,9]
    const float* bias = (const float*)d_in[2];   // [100]
    float* out = (float*)d_out;                  // [8,100,248,248]

    int n = B_ * IC_ * H_ * (GA_P / 8);          // 1.69M threads (covers weights too)
    prep_all<<<(n + 255) / 256, 256>>>(wt, pic);

    cudaFuncSetAttribute(conv_hmma, cudaFuncAttributeMaxDynamicSharedMemorySize, SMEM_TOTAL);
    dim3 grid(2, OH_ / 2, B_);
    conv_hmma<<<grid, NTHR, SMEM_TOTAL>>>(bias, out);
}

// round 17
// speedup vs baseline: 1.0803x; 1.0154x over previous
#include <cuda_runtime.h>
#include <cuda_fp16.h>
#include <cstdint>

// ---------------- problem constants ----------------
#define KH_ 9
#define KW_ 9
#define IC_ 25
#define OC_ 100
#define H_  256
#define W_  256
#define OH_ 248
#define OW_ 248
#define B_  8

// ---------------- GEMM config ----------------
#define KWP 10            // kw padded 9 -> 10
#define NOC 104           // oc padded 100 -> 104 (13 n8 chunks: 6+6 +shared 13th)
#define NTHR 512          // 16 warps; M = 256 px (2 output rows x 128)
#define NAROWS 26         // 25 ic + zero row for k-pad

// B full-K tiles: 256 k-elems (250 real + pad), pitch 264 = 528 B (4-bank stride)
#define BPITCH 264
#define BROWB  528
#define BTILE  (NOC*BROWB)       // 54912 B
#define NSEG   9                 // one segment per kh (full K)

// A: per input row, even + odd-shift parity copies; 4-slot ring keyed by row&3
#define APITCH 144
#define AROWB (APITCH*2)         // 288 B
#define ACOPY (NAROWS*AROWB)     // 7488
#define ASLOT (2*ACOPY)          // 14976
#define GA_P  264                // padded row length of pre-converted A

// smem layout (bytes)
#define SM_BIAS 0                            // 104 * 4 = 416 B
#define SM_A    512                          // 4 A slots
#define SM_B    (SM_A + 4*ASLOT)             // 512 + 59904 = 60416
#define SMEM_TOTAL (SM_B + 3*BTILE)          // 60416 + 164736 = 225152

// fp16 weights: [kh][oc][k(264)]
__device__ __align__(16) __half g_w[KH_][NOC][BPITCH];
// pre-converted fp16 input, even + odd-shift parity copies
__device__ __align__(16) __half g_ae[B_][IC_][H_][GA_P];
__device__ __align__(16) __half g_ao[B_][IC_][H_][GA_P];

// ---------------- helpers ----------------
__device__ __forceinline__ uint32_t smem_u32(const void* p) {
    uint32_t a;
    asm("{ .reg .u64 t; cvta.to.shared.u64 t, %1; cvt.u32.u64 %0, t; }" : "=r"(a) : "l"(p));
    return a;
}

// lds32 with compile-time immediate offset
template <int IMM>
__device__ __forceinline__ uint32_t lds32i(uint32_t a) {
    uint32_t v;
    asm volatile("ld.shared.b32 %0, [%1+%2];" : "=r"(v) : "r"(a), "n"(IMM));
    return v;
}

template <int IMM>
__device__ __forceinline__ void ldmx4i(uint32_t& r0, uint32_t& r1, uint32_t& r2,
                                       uint32_t& r3, uint32_t addr) {
    asm volatile("ldmatrix.sync.aligned.m8n8.x4.shared.b16 {%0,%1,%2,%3}, [%4+%5];"
                 : "=r"(r0), "=r"(r1), "=r"(r2), "=r"(r3) : "r"(addr), "n"(IMM));
}

__device__ __forceinline__ void ldmx2(uint32_t& r0, uint32_t& r1, uint32_t addr) {
    asm volatile("ldmatrix.sync.aligned.m8n8.x2.shared.b16 {%0,%1}, [%2];"
                 : "=r"(r0), "=r"(r1) : "r"(addr));
}

__device__ __forceinline__ void mma16816(float* d, const uint32_t* a,
                                         uint32_t b0, uint32_t b1) {
    asm volatile(
        "mma.sync.aligned.m16n8k16.row.col.f32.f16.f16.f32 "
        "{%0,%1,%2,%3}, {%4,%5,%6,%7}, {%8,%9}, {%0,%1,%2,%3};"
        : "+f"(d[0]), "+f"(d[1]), "+f"(d[2]), "+f"(d[3])
        : "r"(a[0]), "r"(a[1]), "r"(a[2]), "r"(a[3]), "r"(b0), "r"(b1));
}

__device__ __forceinline__ void cpasync16(uint32_t dst, const void* src) {
    asm volatile("cp.async.cg.shared.global [%0], [%1], 16;"
                 :: "r"(dst), "l"(src));
}

// ---------------- merged prep: weights + vectorized input conversion ----------------
__global__ void prep_all(const float* __restrict__ wt,
                         const float* __restrict__ pic) {
    const int idx = blockIdx.x * blockDim.x + threadIdx.x;

    // weights part
    const int NW = KH_ * NOC * BPITCH;
    if (idx < NW) {
        int kh = idx / (NOC * BPITCH);
        int rem = idx % (NOC * BPITCH);
        int oc = rem / BPITCH;
        int k  = rem % BPITCH;
        float w = 0.f;
        if (oc < OC_ && k < IC_ * KWP) {
            int ic = k / KWP, kw = k % KWP;
            if (kw < KW_)
                w = wt[(((size_t)oc * IC_ + ic) * KH_ + kh) * KW_ + kw];
        }
        g_w[kh][oc][k] = __float2half_rn(w);
    }

    // input part: one thread converts 8 consecutive columns (aligned float4 x2)
    const int total8 = B_ * IC_ * H_ * (GA_P / 8);
    if (idx < total8) {
        int chunk = idx % (GA_P / 8);
        int r     = idx / (GA_P / 8);       // (b*IC + ic)*H + row
        int c0    = chunk * 8;
        const float* prow = pic + (size_t)r * W_;
        float v[9];
        if (c0 + 8 <= W_) {
            float4 f0 = *(const float4*)(prow + c0);
            float4 f1 = *(const float4*)(prow + c0 + 4);
            v[0] = f0.x; v[1] = f0.y; v[2] = f0.z; v[3] = f0.w;
            v[4] = f1.x; v[5] = f1.y; v[6] = f1.z; v[7] = f1.w;
            v[8] = (c0 + 8 < W_) ? prow[c0 + 8] : 0.f;
        } else {
#pragma unroll
            for (int j = 0; j < 9; ++j)
                v[j] = (c0 + j < W_) ? prow[c0 + j] : 0.f;
        }
        ushort he[8], ho[8];
#pragma unroll
        for (int j = 0; j < 8; ++j) {
            he[j] = __half_as_ushort(__float2half_rn(v[j]));
            ho[j] = __half_as_ushort(__float2half_rn(v[j + 1]));
        }
        size_t off = (size_t)r * GA_P + c0;
        *(uint4*)(((__half*)g_ae) + off) = *(uint4*)he;
        *(uint4*)(((__half*)g_ao) + off) = *(uint4*)ho;
    }
}

// ---------------- main kernel ----------------
// block = 256 px (2 output rows x 128) x 104 oc.
// 16 warps: wm = wid&7 (rowi = wm>>2, wmr = wm&3 -> 2 m16-frags),
//           wn = wid>>3. Each column owns 6 n8-chunks; the 13th (global
//           chunk 6) alternates by kc parity and is reduced in the epilogue.
// A fragments software-pipelined one kc ahead (ping-pong registers).
// A frag second half = px+8 = +16 BYTES along the row (not +8 ic-rows!).
__global__ __launch_bounds__(NTHR, 1)
void conv_hmma(const float* __restrict__ bias,
               float* __restrict__ out) {
    extern __shared__ char smem[];
    const uint32_t sb = smem_u32(smem);
    const int tid = threadIdx.x;
    const int lid = tid & 31;
    const int wid = tid >> 5;
    const int wm  = wid & 7;
    const int wn  = wid >> 3;
    const int rowi = wm >> 2;         // 0: output row y0, 1: output row y0+1
    const int wmr  = wm & 3;
    const int g  = lid >> 2;          // 0..7
    const int c4 = (lid & 3) << 1;    // 0,2,4,6
    const int x0 = blockIdx.x ? (OW_ - 128) : 0;
    const int y0 = blockIdx.y * 2;
    const int b  = blockIdx.z;

    // ---- init: zero A slots (pads + zero row persist), stage bias ----
#pragma unroll 1
    for (int i = tid; i < (4 * ASLOT) / 16; i += NTHR)
        *(uint4*)(smem + SM_A + i * 16) = make_uint4(0, 0, 0, 0);
    if (tid < NOC)
        *(float*)(smem + SM_BIAS + tid * 4) = (tid < OC_) ? bias[tid] : 0.f;
    __syncthreads();

#define STAGE_A_ROW(r)                                                          \
    {                                                                           \
        const uint32_t adst = sb + SM_A + (uint32_t)(((r) & 3) * ASLOT);        \
        _Pragma("unroll 1")                                                     \
        for (int i = tid; i < 2 * IC_ * 17; i += NTHR) {                        \
            int p  = i / (IC_ * 17);                                            \
            int rr = i % (IC_ * 17);                                            \
            int ic = rr / 17;                                                   \
            int ch = rr % 17;                                                   \
            const __half* src = (p ? &g_ao[0][0][0][0] : &g_ae[0][0][0][0])     \
                + ((((size_t)b * IC_ + ic) * H_) + (r)) * GA_P + x0 + ch * 8;   \
            cpasync16(adst + (uint32_t)(p * ACOPY + ic * AROWB + ch * 16), src);\
        }                                                                       \
    }

#define STAGE_B(kh, slot)                                                       \
    {                                                                           \
        const char* bsrc = (const char*)(&g_w[(kh)][0][0]);                     \
        const uint32_t bdst = sb + SM_B + (uint32_t)((slot) * BTILE);           \
        _Pragma("unroll 1")                                                     \
        for (int i = tid; i < BTILE / 16; i += NTHR)                            \
            cpasync16(bdst + (uint32_t)(i * 16), bsrc + i * 16);                \
    }

    // ---- prologue ----
    STAGE_A_ROW(y0);
    STAGE_A_ROW(y0 + 1);
    STAGE_B(0, 0);
    asm volatile("cp.async.commit_group;" ::: "memory");
    STAGE_A_ROW(y0 + 2);
    STAGE_B(1, 1);
    asm volatile("cp.async.commit_group;" ::: "memory");

    // ldmatrix per-thread base (chunk pairs at +0, +8448, +16896 immediates)
    const int cb0 = wn * 7;        // wn0 -> chunks 0..5 (+6 shared), wn1 -> 7..12 (+6 shared)
    const int grp = lid >> 3;      // 0..3
    const int tr  = lid & 7;
    const uint32_t bro0 = (uint32_t)(((cb0 + (grp >> 1)) * 8 + tr) * BROWB
                                     + (grp & 1) * 16);
    const uint32_t brx = (uint32_t)((6 * 8 + tr) * BROWB + (grp & 1) * 16); // shared chunk 6

    float acc[2][7][4];
#pragma unroll
    for (int m = 0; m < 2; ++m)
#pragma unroll
        for (int n = 0; n < 7; ++n)
#pragma unroll
            for (int q = 0; q < 4; ++q)
                acc[m][n][q] = 0.f;

    // koff helper (compile-time kc)
#define KOFFS(kcv, koff0, koff1)                                                \
    {                                                                           \
        const int k0 = (kcv) * 16 + c4;                                         \
        const int k1 = k0 + 8;                                                  \
        const int ic0 = (k0 * 6554) >> 16;                                      \
        const int ic1 = (k1 * 6554) >> 16;                                      \
        koff0 = (uint32_t)(ic0 * AROWB + (k0 - ic0 * KWP) * 2);                 \
        koff1 = (uint32_t)(ic1 * AROWB + (k1 - ic1 * KWP) * 2);                 \
    }

    // A fragment: regs {0,1} = (px, px+8) @ k0 ; {2,3} = (px, px+8) @ k1.
    // px+8 is +16 bytes along the same smem row.
#define LOAD_A(dst, ap0, ap1, koff0, koff1)                                     \
    {                                                                           \
        dst[0][0] = lds32i<0>(ap0 + koff0);                                     \
        dst[0][1] = lds32i<16>(ap0 + koff0);                                    \
        dst[0][2] = lds32i<0>(ap0 + koff1);                                     \
        dst[0][3] = lds32i<16>(ap0 + koff1);                                    \
        dst[1][0] = lds32i<0>(ap1 + koff0);                                     \
        dst[1][1] = lds32i<16>(ap1 + koff0);                                    \
        dst[1][2] = lds32i<0>(ap1 + koff1);                                     \
        dst[1][3] = lds32i<16>(ap1 + koff1);                                    \
    }

    // ---- pipelined main loop: one segment per kh ----
#pragma unroll 1
    for (int s = 0; s < NSEG; ++s) {
        if (s < NSEG - 2) {
            asm volatile("cp.async.wait_group 1;" ::: "memory");
        } else {
            asm volatile("cp.async.wait_group 0;" ::: "memory");
        }
        __syncthreads();

        if (s + 2 < NSEG) {
            STAGE_B(s + 2, (s + 2) % 3);
            STAGE_A_ROW(y0 + s + 3);
            asm volatile("cp.async.commit_group;" ::: "memory");
        }

        // ---- compute: 16 kc chunks, full K; A pipelined one kc ahead ----
        const int arow = y0 + s + rowi;
        const uint32_t abase = sb + SM_A + (uint32_t)((arow & 3) * ASLOT)
                             + ((g & 1) ? (uint32_t)(ACOPY - 2) : 0u)
                             + (uint32_t)(g * 2);
        const uint32_t ap0 = abase + (uint32_t)((wmr * 2) * 32);
        const uint32_t ap1 = abase + (uint32_t)((wmr * 2 + 1) * 32);

        const uint32_t qb = sb + SM_B + (uint32_t)((s % 3) * BTILE);
        const uint32_t qb0 = qb + bro0;
        const uint32_t qbx = qb + brx;

        uint32_t areg[2][2][4];
        {
            uint32_t kf0, kf1;
            KOFFS(0, kf0, kf1);
            LOAD_A(areg[0], ap0, ap1, kf0, kf1);
        }

#pragma unroll
        for (int kc = 0; kc < 16; ++kc) {
            uint32_t (*acur)[4] = areg[kc & 1];
            if (kc < 15) {
                uint32_t kf0, kf1;
                KOFFS(kc + 1, kf0, kf1);
                LOAD_A(areg[(kc + 1) & 1], ap0, ap1, kf0, kf1);
            }

            const uint32_t kb = (uint32_t)(kc * 32);
            {
                uint32_t b0, b1, b2, b3;
                ldmx4i<0>(b0, b1, b2, b3, qb0 + kb);
                mma16816(acc[0][0], acur[0], b0, b1);
                mma16816(acc[1][0], acur[1], b0, b1);
                mma16816(acc[0][1], acur[0], b2, b3);
                mma16816(acc[1][1], acur[1], b2, b3);
            }
            {
                uint32_t b0, b1, b2, b3;
                ldmx4i<2 * 8 * BROWB>(b0, b1, b2, b3, qb0 + kb);
                mma16816(acc[0][2], acur[0], b0, b1);
                mma16816(acc[1][2], acur[1], b0, b1);
                mma16816(acc[0][3], acur[0], b2, b3);
                mma16816(acc[1][3], acur[1], b2, b3);
            }
            {
                uint32_t b0, b1, b2, b3;
                ldmx4i<4 * 8 * BROWB>(b0, b1, b2, b3, qb0 + kb);
                mma16816(acc[0][4], acur[0], b0, b1);
                mma16816(acc[1][4], acur[1], b0, b1);
                mma16816(acc[0][5], acur[0], b2, b3);
                mma16816(acc[1][5], acur[1], b2, b3);
            }
            if ((kc & 1) == wn) {   // shared chunk 6, alternating by kc parity
                uint32_t e0, e1;
                ldmx2(e0, e1, qbx + kb);
                mma16816(acc[0][6], acur[0], e0, e1);
                mma16816(acc[1][6], acur[1], e0, e1);
            }
        }
    }

    // ---- cross-column reduction for shared chunk 6 ----
    __syncthreads();   // all compute done; B slots reusable
    float* red = (float*)(smem + SM_B);
    if (wn == 1) {
#pragma unroll
        for (int m = 0; m < 2; ++m)
#pragma unroll
            for (int q = 0; q < 4; ++q)
                red[((wm * 2 + m) * 32 + lid) * 4 + q] = acc[m][6][q];
    }
    __syncthreads();
    if (wn == 0) {
#pragma unroll
        for (int m = 0; m < 2; ++m)
#pragma unroll
            for (int q = 0; q < 4; ++q)
                acc[m][6][q] += red[((wm * 2 + m) * 32 + lid) * 4 + q];
    }

    // ---- epilogue: bias + stores ----
    const int nchunks = (wn == 0) ? 7 : 6;
    const int oy = y0 + rowi;
#pragma unroll
    for (int m = 0; m < 2; ++m) {
        const int px = (wmr * 2 + m) * 16 + g;
#pragma unroll
        for (int nc = 0; nc < 7; ++nc) {
            if (nc >= nchunks) break;
            const int oc = (cb0 + nc) * 8 + c4;
            if (oc < OC_) {
                float bz0 = *(float*)(smem + SM_BIAS + oc * 4);
                float bz1 = *(float*)(smem + SM_BIAS + (oc + 1) * 4);
                size_t base0 = (((size_t)(b * OC_ + oc)) * OH_ + oy) * OW_ + x0;
                size_t base1 = base0 + (size_t)OH_ * OW_;
                out[base0 + px]     = acc[m][nc][0] + bz0;
                out[base1 + px]     = acc[m][nc][1] + bz1;
                out[base0 + px + 8] = acc[m][nc][2] + bz0;
                out[base1 + px + 8] = acc[m][nc][3] + bz1;
            }
        }
    }
#undef STAGE_A_ROW
#undef STAGE_B
#undef KOFFS
#undef LOAD_A
}

// ---------------- launch ----------------
extern "C" void kernel_launch(void* const* d_in, const int* in_sizes, int n_in,
                              void* d_out, int out_size) {
    const float* pic  = (const float*)d_in[0];   // [8,25,256,256]
    const float* wt   = (const float*)d_in[1];   // [100,25,9,9]
    const float* bias = (const float*)d_in[2];   // [100]
    float* out = (float*)d_out;                  // [8,100,248,248]

    int n = B_ * IC_ * H_ * (GA_P / 8);          // covers weight part too
    prep_all<<<(n + 255) / 256, 256>>>(wt, pic);

    cudaFuncSetAttribute(conv_hmma, cudaFuncAttributeMaxDynamicSharedMemorySize, SMEM_TOTAL);
    dim3 grid(2, OH_ / 2, B_);
    conv_hmma<<<grid, NTHR, SMEM_TOTAL>>>(bias, out);
}